// round 3
// baseline (speedup 1.0000x reference)
#include <cuda_runtime.h>
#include <cstdint>

// TSBRNN: B=8192 rows, T=4096 steps, per-row 2-state swap recurrence.
// Parallelized along T: 4 chunks per row; chunks >0 warm up over the
// preceding 512 steps (state influence decays by >=0.9^256 ~ 2e-12, below
// fp32 ulp), so outputs are exact to fp32. 1024 independent warps.

namespace {
constexpr int T_LEN   = 4096;
constexpr int TT      = 64;               // timesteps per tile
constexpr int WROWS   = 32;               // rows per warp (1 row/lane)
constexpr int WARPS   = 4;                // one chunk per warp
constexpr int THREADS = 32 * WARPS;       // 128
constexpr int STAGES  = 3;
constexpr int TILE_F  = WROWS * TT;       // 2048 floats = 8KB / stage
constexpr int WBUF_F  = STAGES * TILE_F;  // per-warp ring (24KB)
constexpr int SMEM_FLOATS = WARPS * WBUF_F + T_LEN;
constexpr int SMEM_BYTES  = SMEM_FLOATS * 4;   // 96KB + 16KB = 112KB
constexpr int WARM    = 512;              // warmup steps (8 tiles)
constexpr int N_TILES = 22;               // tiles per warp (uniform)
__constant__ int CHUNK_START_C[4] = {0, 1408, 2304, 3200};
}

__device__ __forceinline__ void cp_async16(uint32_t dst, const void* src) {
    asm volatile("cp.async.cg.shared.global [%0], [%1], 16;\n" :: "r"(dst), "l"(src));
}
__device__ __forceinline__ void cp_commit() {
    asm volatile("cp.async.commit_group;\n" ::: "memory");
}
template <int N>
__device__ __forceinline__ void cp_wait() {
    asm volatile("cp.async.wait_group %0;\n" :: "n"(N) : "memory");
}

__global__ void __launch_bounds__(THREADS, 2)
tsb_kernel(const float* __restrict__ x, const float* __restrict__ alpha_p,
           const float* __restrict__ beta_p, float* __restrict__ out) {
    extern __shared__ float smem[];
    float* aX = smem + WARPS * WBUF_F;   // alpha * x[0, t]

    const int tid  = threadIdx.x;
    const int wid  = tid >> 5;
    const int lane = tid & 31;
    const float alpha  = __ldg(alpha_p);
    const float beta   = __ldg(beta_p);
    const float omb    = 1.0f - beta;
    const float nalpha = -alpha;

    // Stage the global level-driver sequence once per CTA
#pragma no_unroll
    for (int i = tid; i < T_LEN / 4; i += THREADS) {
        float4 v = __ldg(reinterpret_cast<const float4*>(x) + i);
        v.x *= alpha; v.y *= alpha; v.z *= alpha; v.w *= alpha;
        reinterpret_cast<float4*>(aX)[i] = v;
    }
    __syncthreads();   // only barrier

    const int chunk    = wid;
    const int t_start  = CHUNK_START_C[chunk];
    const int t_load0  = (chunk == 0) ? 0 : t_start - WARM;
    const int warm_tl  = (chunk == 0) ? 0 : WARM / TT;   // 0 or 8

    const int row_base = blockIdx.x * WROWS;
    float* wbuf = smem + wid * WBUF_F;
    const uint32_t wbuf_sa = (uint32_t)__cvta_generic_to_shared(wbuf);
    const float* xbase = x + (size_t)row_base * T_LEN + t_load0;

    // Per-warp tile load: 16 cp.async/lane, coalesced global, XOR-swizzled smem
    auto load_tile = [&](int tile, int slot) {
        uint32_t sbase = wbuf_sa + (uint32_t)(slot * TILE_F) * 4u;
#pragma unroll
        for (int i = 0; i < 16; ++i) {
            int idx = lane + 32 * i;       // 0..511 (32 rows x 16 float4)
            int row = idx >> 4;
            int j4  = idx & 15;
            int js  = j4 ^ (row & 7);      // conflict-free for compute LDS.128
            const float* src = xbase + (size_t)row * T_LEN + tile * TT + j4 * 4;
            cp_async16(sbase + (uint32_t)(row * TT + js * 4) * 4u, src);
        }
    };

#pragma unroll
    for (int k = 0; k < STAGES; ++k) {
        load_tile(k, k);
        cp_commit();
    }

    float A = 0.0f, Bs = 0.0f;
    const int swz = lane & 7;
    float* og_row = out + (size_t)(row_base + lane) * T_LEN + t_load0;

#define TSB_STEP(xval, aval, oval)                      \
    {                                                   \
        float nz  = fminf(fabsf(xval), 1.0f);           \
        float bnz = fminf(fabsf(xval), beta);           \
        float t1  = fmaf(nalpha, A, aval);              \
        float Bn  = fmaf(nz, t1, A);                    \
        float An  = fmaf(Bs, omb, bnz);                 \
        oval = An * Bn; A = An; Bs = Bn;                \
    }

    for (int tile = 0; tile < N_TILES; ++tile) {
        cp_wait<STAGES - 1>();   // per-thread cp.async group state

        const float* xr  = wbuf + (tile % STAGES) * TILE_F + lane * TT;
        const float* aXt = aX + t_load0 + tile * TT;
        float* og = og_row + tile * TT;
        const bool emit = (tile >= warm_tl);

#pragma unroll
        for (int j8 = 0; j8 < TT / 8; ++j8) {
            int j4a = (2 * j8) ^ swz;
            int j4b = j4a ^ 1;
            float4 xv0 = *reinterpret_cast<const float4*>(xr + j4a * 4);
            float4 xv1 = *reinterpret_cast<const float4*>(xr + j4b * 4);
            float4 av0 = *reinterpret_cast<const float4*>(aXt + j8 * 8);
            float4 av1 = *reinterpret_cast<const float4*>(aXt + j8 * 8 + 4);
            float4 o0, o1;
            TSB_STEP(xv0.x, av0.x, o0.x);
            TSB_STEP(xv0.y, av0.y, o0.y);
            TSB_STEP(xv0.z, av0.z, o0.z);
            TSB_STEP(xv0.w, av0.w, o0.w);
            TSB_STEP(xv1.x, av1.x, o1.x);
            TSB_STEP(xv1.y, av1.y, o1.y);
            TSB_STEP(xv1.z, av1.z, o1.z);
            TSB_STEP(xv1.w, av1.w, o1.w);
            if (emit) {   // 32B-aligned pair -> fully-written DRAM sector
                *reinterpret_cast<float4*>(og + j8 * 8)     = o0;
                *reinterpret_cast<float4*>(og + j8 * 8 + 4) = o1;
            }
        }

        int nt = tile + STAGES;
        if (nt < N_TILES)
            load_tile(nt, nt % STAGES);
        cp_commit();   // keep wait_group accounting aligned
    }
#undef TSB_STEP
}

extern "C" void kernel_launch(void* const* d_in, const int* in_sizes, int n_in,
                              void* d_out, int out_size) {
    const float* x       = (const float*)d_in[0];   // (B, T, 1) float32
    const float* alpha_p = (const float*)d_in[1];   // (1, 1)
    const float* beta_p  = (const float*)d_in[2];   // (1, 1)
    float* out = (float*)d_out;

    int batch = in_sizes[0] / T_LEN;                // 8192
    int grid  = batch / WROWS;                      // 256 CTAs x 4 warps

    cudaFuncSetAttribute(tsb_kernel, cudaFuncAttributeMaxDynamicSharedMemorySize,
                         SMEM_BYTES);
    tsb_kernel<<<grid, THREADS, SMEM_BYTES>>>(x, alpha_p, beta_p, out);
}

// round 4
// speedup vs baseline: 1.0887x; 1.0887x over previous
#include <cuda_runtime.h>
#include <cstdint>

// TSBRNN: B=8192 rows, T=4096. Per-row 2-state swap recurrence:
//   Bn = A + nz*(alpha*X_t - alpha*A); An = (1-beta)*Bs + beta*nz; out = An*Bn
// X_t = x[0,t]. T split 2-way per row; second chunk warms up 256 steps
// (state error contracts >= 0.9 per 2 steps -> <= 1.4e-6 worst case).
// 256 CTAs x 2 warps, 5-stage cp.async ring, register-accumulated stores.

namespace {
constexpr int T_LEN   = 4096;
constexpr int TT      = 64;               // timesteps per tile
constexpr int WROWS   = 32;               // rows per warp (1 row/lane)
constexpr int WARPS   = 2;                // 2 T-chunks of the same 32 rows
constexpr int THREADS = 32 * WARPS;       // 64
constexpr int STAGES  = 5;
constexpr int TILE_F  = WROWS * TT;       // 2048 floats = 8KB / stage
constexpr int WBUF_F  = STAGES * TILE_F;  // 40KB per warp
constexpr int SMEM_FLOATS = WARPS * WBUF_F + T_LEN;
constexpr int SMEM_BYTES  = SMEM_FLOATS * 4;   // 80KB + 16KB = 96KB
constexpr int WARM       = 256;           // warmup steps for chunk 1 (4 tiles)
constexpr int E0         = 2176;          // chunk-0 emit length (34 tiles)
constexpr int N_TILES    = 34;            // uniform tiles per warp
constexpr int WARM_TILES = WARM / TT;     // 4
}

__device__ __forceinline__ void cp_async16(uint32_t dst, const void* src) {
    asm volatile("cp.async.cg.shared.global [%0], [%1], 16;\n" :: "r"(dst), "l"(src));
}
__device__ __forceinline__ void cp_commit() {
    asm volatile("cp.async.commit_group;\n" ::: "memory");
}
template <int N>
__device__ __forceinline__ void cp_wait() {
    asm volatile("cp.async.wait_group %0;\n" :: "n"(N) : "memory");
}

__global__ void __launch_bounds__(THREADS, 2)
tsb_kernel(const float* __restrict__ x, const float* __restrict__ alpha_p,
           const float* __restrict__ beta_p, float* __restrict__ out) {
    extern __shared__ float smem[];
    float* aX = smem + WARPS * WBUF_F;   // alpha * x[0, t]

    const int tid  = threadIdx.x;
    const int wid  = tid >> 5;
    const int lane = tid & 31;
    const float alpha  = __ldg(alpha_p);
    const float beta   = __ldg(beta_p);
    const float omb    = 1.0f - beta;
    const float nalpha = -alpha;

    // Stage the global level-driver sequence once per CTA
#pragma no_unroll
    for (int i = tid; i < T_LEN / 4; i += THREADS) {
        float4 v = __ldg(reinterpret_cast<const float4*>(x) + i);
        v.x *= alpha; v.y *= alpha; v.z *= alpha; v.w *= alpha;
        reinterpret_cast<float4*>(aX)[i] = v;
    }
    __syncthreads();   // only barrier

    // Warp 0: steps [0, 2176) all emitted.
    // Warp 1: loads from 1920; tiles 0..3 warm up, emits [2176, 4096).
    const int t_load0 = (wid == 0) ? 0 : (E0 - WARM);   // 0 or 1920
    const int warm_tl = (wid == 0) ? 0 : WARM_TILES;

    const int row_base = blockIdx.x * WROWS;
    float* wbuf = smem + wid * WBUF_F;
    const uint32_t wbuf_sa = (uint32_t)__cvta_generic_to_shared(wbuf);
    const float* xbase = x + (size_t)row_base * T_LEN + t_load0;

    // Per-warp tile load: 16 cp.async/lane, coalesced global, XOR-swizzled smem
    auto load_tile = [&](int tile, int slot) {
        uint32_t sbase = wbuf_sa + (uint32_t)(slot * TILE_F) * 4u;
#pragma unroll
        for (int i = 0; i < 16; ++i) {
            int idx = lane + 32 * i;       // 0..511 (32 rows x 16 float4)
            int row = idx >> 4;
            int j4  = idx & 15;
            int js  = j4 ^ (row & 7);      // conflict-free for compute LDS.128
            const float* src = xbase + (size_t)row * T_LEN + tile * TT + j4 * 4;
            cp_async16(sbase + (uint32_t)(row * TT + js * 4) * 4u, src);
        }
    };

#pragma unroll
    for (int k = 0; k < STAGES; ++k) {
        load_tile(k, k);
        cp_commit();
    }

    float A = 0.0f, Bs = 0.0f;
    const int swz = lane & 7;
    float* og_row = out + (size_t)(row_base + lane) * T_LEN + t_load0;

#define TSB_STEP(xval, aval, oval)                      \
    {                                                   \
        float nz  = fminf(fabsf(xval), 1.0f);           \
        float bnz = fminf(fabsf(xval), beta);           \
        float t1  = fmaf(nalpha, A, aval);              \
        float Bn  = fmaf(nz, t1, A);                    \
        float An  = fmaf(Bs, omb, bnz);                 \
        oval = An * Bn; A = An; Bs = Bn;                \
    }

    for (int tile = 0; tile < N_TILES; ++tile) {
        cp_wait<STAGES - 1>();   // per-thread cp.async group state

        const float* xr  = wbuf + (tile % STAGES) * TILE_F + lane * TT;
        const float* aXt = aX + t_load0 + tile * TT;
        float* og = og_row + tile * TT;
        const bool emit = (tile >= warm_tl);

#pragma unroll
        for (int j8 = 0; j8 < TT / 8; ++j8) {
            int j4a = (2 * j8) ^ swz;
            int j4b = j4a ^ 1;
            float4 xv0 = *reinterpret_cast<const float4*>(xr + j4a * 4);
            float4 xv1 = *reinterpret_cast<const float4*>(xr + j4b * 4);
            float4 av0 = *reinterpret_cast<const float4*>(aXt + j8 * 8);
            float4 av1 = *reinterpret_cast<const float4*>(aXt + j8 * 8 + 4);
            float4 o0, o1;
            TSB_STEP(xv0.x, av0.x, o0.x);
            TSB_STEP(xv0.y, av0.y, o0.y);
            TSB_STEP(xv0.z, av0.z, o0.z);
            TSB_STEP(xv0.w, av0.w, o0.w);
            TSB_STEP(xv1.x, av1.x, o1.x);
            TSB_STEP(xv1.y, av1.y, o1.y);
            TSB_STEP(xv1.z, av1.z, o1.z);
            TSB_STEP(xv1.w, av1.w, o1.w);
            if (emit) {   // 32B-aligned pair -> fully-written DRAM sector
                *reinterpret_cast<float4*>(og + j8 * 8)     = o0;
                *reinterpret_cast<float4*>(og + j8 * 8 + 4) = o1;
            }
        }

        int nt = tile + STAGES;
        if (nt < N_TILES)
            load_tile(nt, nt % STAGES);
        cp_commit();   // keep wait_group accounting aligned
    }
#undef TSB_STEP
}

extern "C" void kernel_launch(void* const* d_in, const int* in_sizes, int n_in,
                              void* d_out, int out_size) {
    const float* x       = (const float*)d_in[0];   // (B, T, 1) float32
    const float* alpha_p = (const float*)d_in[1];   // (1, 1)
    const float* beta_p  = (const float*)d_in[2];   // (1, 1)
    float* out = (float*)d_out;

    int batch = in_sizes[0] / T_LEN;                // 8192
    int grid  = batch / WROWS;                      // 256 CTAs

    cudaFuncSetAttribute(tsb_kernel, cudaFuncAttributeMaxDynamicSharedMemorySize,
                         SMEM_BYTES);
    tsb_kernel<<<grid, THREADS, SMEM_BYTES>>>(x, alpha_p, beta_p, out);
}

// round 5
// speedup vs baseline: 1.2362x; 1.1354x over previous
#include <cuda_runtime.h>
#include <cuda.h>
#include <cstdint>

// TSBRNN: B=8192 rows, T=4096. Per-row 2-state swap recurrence, out = P'*Z'.
// R5: full-TMA dataflow. Per warp: 32 rows, 64 tiles of 64 steps.
//   in:  UTMALDG 2x[32x32f] SW128 boxes per tile -> 6-stage smem ring (mbarrier)
//   out: compute -> STS (same swizzle) -> UTMASTG from 3-stage ring (bulk_group)
// Bypasses the per-SM L1tex LDG queue that capped prior rounds at ~4 TB/s.

namespace {
constexpr int T_LEN      = 4096;
constexpr int TT         = 64;              // steps per tile (2 TMA boxes of 32)
constexpr int NT         = T_LEN / TT;      // 64 tiles
constexpr int WROWS      = 32;              // rows per warp
constexpr int WARPS      = 2;
constexpr int THREADS    = 64;
constexpr int IN_STAGES  = 6;
constexpr int OUT_STAGES = 3;
constexpr int STAGE_F    = WROWS * TT;      // 2048 floats = 8KB
constexpr int WIN_F      = IN_STAGES * STAGE_F;    // 12288
constexpr int WOUT_F     = OUT_STAGES * STAGE_F;   // 6144
constexpr int WBUF_F     = WIN_F + WOUT_F;         // 18432
constexpr int AX_OFF_F   = WARPS * WBUF_F;         // 36864
constexpr int BAR_OFF_F  = AX_OFF_F + T_LEN;       // 40960 floats
constexpr int SMEM_BYTES = BAR_OFF_F * 4 + WARPS * IN_STAGES * 8 + 32; // ~164KB
}

__device__ __forceinline__ void mbar_init(uint32_t a) {
    asm volatile("mbarrier.init.shared.b64 [%0], 1;" :: "r"(a) : "memory");
}
__device__ __forceinline__ void mbar_expect_tx(uint32_t a, uint32_t bytes) {
    asm volatile("mbarrier.arrive.expect_tx.shared.b64 _, [%0], %1;"
                 :: "r"(a), "r"(bytes) : "memory");
}
__device__ __forceinline__ void mbar_wait(uint32_t a, uint32_t parity) {
    asm volatile(
        "{\n\t.reg .pred P;\n"
        "W%=:\n\t"
        "mbarrier.try_wait.parity.acquire.cta.shared::cta.b64 P, [%0], %1, 0x989680;\n\t"
        "@P bra D%=;\n\t"
        "bra W%=;\n"
        "D%=:\n\t}"
        :: "r"(a), "r"(parity) : "memory");
}
__device__ __forceinline__ void tma_load_2d(uint32_t dst, const CUtensorMap* m,
                                            int cx, int cy, uint32_t bar) {
    asm volatile(
        "cp.async.bulk.tensor.2d.shared::cta.global.tile.mbarrier::complete_tx::bytes "
        "[%0], [%1, {%2, %3}], [%4];"
        :: "r"(dst), "l"(m), "r"(cx), "r"(cy), "r"(bar) : "memory");
}
__device__ __forceinline__ void tma_store_2d(const CUtensorMap* m, int cx, int cy,
                                             uint32_t src) {
    asm volatile(
        "cp.async.bulk.tensor.2d.global.shared::cta.tile.bulk_group "
        "[%0, {%1, %2}], [%3];"
        :: "l"(m), "r"(cx), "r"(cy), "r"(src) : "memory");
}
__device__ __forceinline__ void tma_store_commit() {
    asm volatile("cp.async.bulk.commit_group;" ::: "memory");
}
template <int N>
__device__ __forceinline__ void tma_store_wait_read() {
    asm volatile("cp.async.bulk.wait_group.read %0;" :: "n"(N) : "memory");
}

__global__ void __launch_bounds__(THREADS, 1)
tsb_kernel(const __grid_constant__ CUtensorMap tmx,
           const __grid_constant__ CUtensorMap tmo,
           const float* __restrict__ x,
           const float* __restrict__ alpha_p,
           const float* __restrict__ beta_p) {
    extern __shared__ __align__(1024) float smem[];
    float* aX = smem + AX_OFF_F;

    const int tid  = threadIdx.x;
    const int wid  = tid >> 5;
    const int lane = tid & 31;
    const float alpha  = __ldg(alpha_p);
    const float beta   = __ldg(beta_p);
    const float omb    = 1.0f - beta;
    const float nalpha = -alpha;

    const uint32_t smem_sa = (uint32_t)__cvta_generic_to_shared(smem);
    const uint32_t bar_base = smem_sa + (uint32_t)BAR_OFF_F * 4u;

    // mbarrier init (before the one CTA barrier)
    if (tid == 0) {
        for (int i = 0; i < WARPS * IN_STAGES; ++i)
            mbar_init(bar_base + i * 8);
        asm volatile("fence.proxy.async.shared::cta;" ::: "memory");
    }

    // Stage the global level-driver sequence: aX[t] = alpha * x[0][t]
#pragma no_unroll
    for (int i = tid; i < T_LEN / 4; i += THREADS) {
        float4 v = __ldg(reinterpret_cast<const float4*>(x) + i);
        v.x *= alpha; v.y *= alpha; v.z *= alpha; v.w *= alpha;
        reinterpret_cast<float4*>(aX)[i] = v;
    }
    __syncthreads();   // only CTA barrier

    const int row_base = blockIdx.x * (WARPS * WROWS) + wid * WROWS;
    const uint32_t in_sa  = smem_sa + (uint32_t)(wid * WBUF_F) * 4u;
    const uint32_t out_sa = in_sa + (uint32_t)WIN_F * 4u;
    const uint32_t wbar   = bar_base + (uint32_t)(wid * IN_STAGES) * 8u;

    // Prologue: fill the input ring
    if (lane == 0) {
#pragma unroll
        for (int k = 0; k < IN_STAGES; ++k) {
            uint32_t bar = wbar + k * 8;
            uint32_t dst = in_sa + (uint32_t)(k * STAGE_F) * 4u;
            mbar_expect_tx(bar, STAGE_F * 4);
            tma_load_2d(dst,        &tmx, k * TT,      row_base, bar);
            tma_load_2d(dst + 4096, &tmx, k * TT + 32, row_base, bar);
        }
    }

    float A = 0.0f, Bs = 0.0f;
    const int swz = lane & 7;
    float* myin_base  = smem + wid * WBUF_F + lane * 32;           // + slot*STAGE_F + sub
    float* myout_base = smem + wid * WBUF_F + WIN_F + lane * 32;

#define TSB_STEP(xval, aval, oval)                      \
    {                                                   \
        float nz  = fminf(fabsf(xval), 1.0f);           \
        float bnz = fminf(fabsf(xval), beta);           \
        float t1  = fmaf(nalpha, A, aval);              \
        float Bn  = fmaf(nz, t1, A);                    \
        float An  = fmaf(Bs, omb, bnz);                 \
        oval = An * Bn; A = An; Bs = Bn;                \
    }

    int slot = 0, phase = 0, oslot = 0;
    for (int tile = 0; tile < NT; ++tile) {
        // Gate output-slot reuse: TMA store issued OUT_STAGES tiles ago must
        // have finished READING smem before we overwrite the slot.
        if (lane == 0) tma_store_wait_read<OUT_STAGES - 1>();
        __syncwarp();
        // Wait for this tile's input
        mbar_wait(wbar + slot * 8, (uint32_t)phase);

        const float* xr  = myin_base + slot * STAGE_F;
        float*       orw = myout_base + oslot * STAGE_F;
        const float* aXt = aX + tile * TT;

#pragma unroll
        for (int j8 = 0; j8 < 8; ++j8) {
            int sub = (j8 >> 2) * 1024;                 // 4KB TMA sub-box
            int jj  = (j8 & 3) * 2;
            int ja  = ((jj    ) ^ swz) * 4;
            int jb  = ((jj + 1) ^ swz) * 4;
            float4 xv0 = *reinterpret_cast<const float4*>(xr + sub + ja);
            float4 xv1 = *reinterpret_cast<const float4*>(xr + sub + jb);
            float4 av0 = *reinterpret_cast<const float4*>(aXt + j8 * 8);
            float4 av1 = *reinterpret_cast<const float4*>(aXt + j8 * 8 + 4);
            float4 o0, o1;
            TSB_STEP(xv0.x, av0.x, o0.x);
            TSB_STEP(xv0.y, av0.y, o0.y);
            TSB_STEP(xv0.z, av0.z, o0.z);
            TSB_STEP(xv0.w, av0.w, o0.w);
            TSB_STEP(xv1.x, av1.x, o1.x);
            TSB_STEP(xv1.y, av1.y, o1.y);
            TSB_STEP(xv1.z, av1.z, o1.z);
            TSB_STEP(xv1.w, av1.w, o1.w);
            *reinterpret_cast<float4*>(orw + sub + ja) = o0;
            *reinterpret_cast<float4*>(orw + sub + jb) = o1;
        }

        __syncwarp();   // all lanes' STS done (and ordered) before async-proxy read
        if (lane == 0) {
            asm volatile("fence.proxy.async.shared::cta;" ::: "memory");
            uint32_t osrc = out_sa + (uint32_t)(oslot * STAGE_F) * 4u;
            tma_store_2d(&tmo, tile * TT,      row_base, osrc);
            tma_store_2d(&tmo, tile * TT + 32, row_base, osrc + 4096);
            tma_store_commit();
            // Refill the input slot just consumed
            int nt = tile + IN_STAGES;
            if (nt < NT) {
                uint32_t bar = wbar + slot * 8;
                uint32_t dst = in_sa + (uint32_t)(slot * STAGE_F) * 4u;
                mbar_expect_tx(bar, STAGE_F * 4);
                tma_load_2d(dst,        &tmx, nt * TT,      row_base, bar);
                tma_load_2d(dst + 4096, &tmx, nt * TT + 32, row_base, bar);
            }
        }
        if (++slot == IN_STAGES) { slot = 0; phase ^= 1; }
        if (++oslot == OUT_STAGES) oslot = 0;
    }
#undef TSB_STEP

    if (lane == 0) tma_store_wait_read<0>();   // drain stores before exit
}

extern "C" void kernel_launch(void* const* d_in, const int* in_sizes, int n_in,
                              void* d_out, int out_size) {
    const float* x       = (const float*)d_in[0];   // (B, T, 1) float32
    const float* alpha_p = (const float*)d_in[1];
    const float* beta_p  = (const float*)d_in[2];
    float* out = (float*)d_out;

    int batch = in_sizes[0] / T_LEN;                // 8192
    int grid  = batch / (WARPS * WROWS);            // 128 CTAs

    // Driver entry point via runtime API (no -lcuda needed)
    typedef CUresult (*EncodeFn)(CUtensorMap*, CUtensorMapDataType, cuuint32_t,
                                 void*, const cuuint64_t*, const cuuint64_t*,
                                 const cuuint32_t*, const cuuint32_t*,
                                 CUtensorMapInterleave, CUtensorMapSwizzle,
                                 CUtensorMapL2promotion, CUtensorMapFloatOOBfill);
    static EncodeFn enc = nullptr;
    if (!enc) {
        void* fn = nullptr;
        cudaDriverEntryPointQueryResult st;
        cudaGetDriverEntryPoint("cuTensorMapEncodeTiled", &fn,
                                cudaEnableDefault, &st);
        enc = (EncodeFn)fn;
    }

    cuuint64_t dims[2]    = {(cuuint64_t)T_LEN, (cuuint64_t)batch};
    cuuint64_t strides[1] = {(cuuint64_t)T_LEN * 4};
    cuuint32_t box[2]     = {32u, 32u};
    cuuint32_t es[2]      = {1u, 1u};

    CUtensorMap tmx, tmo;
    enc(&tmx, CU_TENSOR_MAP_DATA_TYPE_FLOAT32, 2, (void*)x, dims, strides,
        box, es, CU_TENSOR_MAP_INTERLEAVE_NONE, CU_TENSOR_MAP_SWIZZLE_128B,
        CU_TENSOR_MAP_L2_PROMOTION_L2_128B, CU_TENSOR_MAP_FLOAT_OOB_FILL_NONE);
    enc(&tmo, CU_TENSOR_MAP_DATA_TYPE_FLOAT32, 2, (void*)out, dims, strides,
        box, es, CU_TENSOR_MAP_INTERLEAVE_NONE, CU_TENSOR_MAP_SWIZZLE_128B,
        CU_TENSOR_MAP_L2_PROMOTION_L2_128B, CU_TENSOR_MAP_FLOAT_OOB_FILL_NONE);

    static bool attr_set = false;
    if (!attr_set) {
        cudaFuncSetAttribute(tsb_kernel,
                             cudaFuncAttributeMaxDynamicSharedMemorySize,
                             SMEM_BYTES);
        attr_set = true;
    }
    tsb_kernel<<<grid, THREADS, SMEM_BYTES>>>(tmx, tmo, x, alpha_p, beta_p);
}